// round 5
// baseline (speedup 1.0000x reference)
#include <cuda_runtime.h>
#include <cuda_fp16.h>
#include <cstdint>
#include <cstddef>

// ----------------------------------------------------------------------------
// CrossAttention_30056181138117 on GB300 (sm_103a) — round 5
//
// (harness compiles via compute_103 family PTX -> tcgen05 unavailable; this is
// the tuned legacy-HMMA path)
//
// Seq-len-1 attention => softmax == 1 => attn out == V projection, folded:
//   att_s = x_other @ Wc_s^T + c_s,  Wc_s = out_w_s @ wv_s
// Per stream: h = LN(x + att); u = relu(h@w1^T+b1); o = LN(h + u@w2^T+b2)
//
// Round-5: 4-stage cp.async pipeline (prefetch distance 3, wait_group 2),
// SINGLE __syncthreads per K-iter, both streams batched per launch (grid.z=2).
// ----------------------------------------------------------------------------

#define MROWS 32768
#define EDIM  512
#define FFDIM 1024

#define BM 128
#define BN 128
#define BK 32
#define NSTAGE 4
#define LDS 40                          // halfs per smem row (80B, 16B-aligned)
#define ASTG (BM * LDS)                 // halfs per A stage
#define WSTG (BN * LDS)                 // halfs per W stage
#define GEMM_SMEM (NSTAGE * (ASTG + WSTG) * 2)   // 81920 bytes

// ------------------------- device scratch (static, no allocs) ---------------
__device__ __half g_xh[2][MROWS * EDIM];
__device__ __half g_h [2][MROWS * EDIM];
__device__ __half g_u [2][MROWS * FFDIM];
__device__ __half g_t [2][MROWS * EDIM];
__device__ __half g_wc[2][EDIM * EDIM];
__device__ float  g_c [2][EDIM];
__device__ __half g_w1h[2][FFDIM * EDIM];
__device__ __half g_w2h[2][EDIM * FFDIM];

struct GemmArgs {
    const __half* A[2];
    const __half* W[2];
    const float*  bias[2];
    const __half* res[2];
    __half*       out[2];
};
struct LnArgs {
    const __half* x[2];
    const float*  g[2];
    const float*  b[2];
    __half*       outh[2];   // or null
    float*        outf;      // strided fp32 out base, or null
};

// ------------------------- helpers -------------------------------------------
__device__ __forceinline__ void cp_async16(uint32_t dst, const void* src) {
    asm volatile("cp.async.cg.shared.global [%0], [%1], 16;\n" :: "r"(dst), "l"(src));
}
__device__ __forceinline__ void ldsm_x4(uint32_t& r0, uint32_t& r1,
                                        uint32_t& r2, uint32_t& r3, uint32_t addr) {
    asm volatile("ldmatrix.sync.aligned.m8n8.x4.shared.b16 {%0,%1,%2,%3}, [%4];"
                 : "=r"(r0), "=r"(r1), "=r"(r2), "=r"(r3) : "r"(addr));
}

// ------------------------- small kernels -------------------------------------
__global__ void k_f2h(const float* __restrict__ src, __half* __restrict__ dst, int n) {
    int i = (blockIdx.x * blockDim.x + threadIdx.x) * 4;
    if (i >= n) return;
    float4 v = *(const float4*)(src + i);
    __half2* d = (__half2*)(dst + i);
    d[0] = __floats2half2_rn(v.x, v.y);
    d[1] = __floats2half2_rn(v.z, v.w);
}

__global__ void k_fold(const float* __restrict__ out_w,
                       const float* __restrict__ wv,
                       __half* __restrict__ wc) {
    __shared__ float srow[EDIM];
    int i = blockIdx.x, k = threadIdx.x;
    srow[k] = out_w[i * EDIM + k];
    __syncthreads();
    float acc = 0.f;
#pragma unroll 4
    for (int j = 0; j < EDIM; j++) acc = fmaf(srow[j], wv[j * EDIM + k], acc);
    wc[i * EDIM + k] = __float2half(acc);
}

__global__ void k_foldc(const float* __restrict__ out_w,
                        const float* __restrict__ out_b,
                        const float* __restrict__ bv,
                        float* __restrict__ c) {
    int i = blockIdx.x * blockDim.x + threadIdx.x;
    if (i >= EDIM) return;
    float acc = out_b[i];
    for (int j = 0; j < EDIM; j++) acc = fmaf(out_w[i * EDIM + j], bv[j], acc);
    c[i] = acc;
}

// ------------------------- fp16 HMMA GEMM -------------------------------------
// z = blockIdx.z selects the stream. out[r][n] = sum_k A[r][k]*W[n][k]
// (+bias, opt relu, opt fp16 residual) -> fp16
template <int K>
__global__ __launch_bounds__(256, 2) void k_gemm(GemmArgs ga, int N, int relu)
{
    constexpr int NT = K / BK;
    const int z = blockIdx.z;
    const __half* __restrict__ A    = ga.A[z];
    const __half* __restrict__ W    = ga.W[z];
    const float*  __restrict__ bias = ga.bias[z];
    const __half* __restrict__ resh = ga.res[z];
    __half*       __restrict__ outh = ga.out[z];

    extern __shared__ __half smem[];
    __half* Asm = smem;
    __half* Wsm = smem + NSTAGE * ASTG;
    const uint32_t as_u = (uint32_t)__cvta_generic_to_shared(Asm);
    const uint32_t ws_u = (uint32_t)__cvta_generic_to_shared(Wsm);

    const int t = threadIdx.x;
    const int warp = t >> 5, lane = t & 31;
    const int g = lane >> 2, tg = lane & 3;
    const int brow = blockIdx.y * BM;
    const int bcol = blockIdx.x * BN;
    const int wm = (warp >> 1) * 32;
    const int wn = (warp & 1) * 64;

    const int lr = t >> 2;
    const int lc = (t & 3) * 8;
    const __half* Ag = A + (size_t)(brow + lr) * K + lc;
    const __half* Wg = W + (size_t)(bcol + lr) * K + lc;

    const int arow = lane & 15;
    const int acol = (lane & 16) >> 1;
    const int browl = (lane & 7) + ((lane & 16) >> 1);
    const int bcoll = lane & 8;

    float acc[2][8][4];
#pragma unroll
    for (int a = 0; a < 2; a++)
#pragma unroll
        for (int b = 0; b < 8; b++)
#pragma unroll
            for (int c = 0; c < 4; c++) acc[a][b][c] = 0.f;

    auto load_stage = [&](int i, int slot) {
        const int ko = i * BK;
        const uint32_t as = as_u + slot * ASTG * 2;
        const uint32_t ws = ws_u + slot * WSTG * 2;
        cp_async16(as + (lr * LDS + lc) * 2,        Ag + ko);
        cp_async16(as + ((lr + 64) * LDS + lc) * 2, Ag + ko + (size_t)64 * K);
        cp_async16(ws + (lr * LDS + lc) * 2,        Wg + ko);
        cp_async16(ws + ((lr + 64) * LDS + lc) * 2, Wg + ko + (size_t)64 * K);
        asm volatile("cp.async.commit_group;\n");
    };

    // prologue: fill 3 of 4 slots
    load_stage(0, 0);
    load_stage(1, 1);
    load_stage(2, 2);

#pragma unroll 4
    for (int i = 0; i < NT; i++) {
        if (i < NT - 2)      asm volatile("cp.async.wait_group 2;\n");
        else if (i == NT - 2) asm volatile("cp.async.wait_group 1;\n");
        else                  asm volatile("cp.async.wait_group 0;\n");
        __syncthreads();   // single barrier per K-iter

        if (i + 3 < NT) load_stage(i + 3, (i + 3) & (NSTAGE - 1));

        const int s = i & (NSTAGE - 1);
        const uint32_t as = as_u + s * ASTG * 2;
        const uint32_t ws = ws_u + s * WSTG * 2;

#pragma unroll
        for (int kk = 0; kk < BK; kk += 16) {
            uint32_t ra[2][4], rb[8][2];
#pragma unroll
            for (int mi = 0; mi < 2; mi++)
                ldsm_x4(ra[mi][0], ra[mi][1], ra[mi][2], ra[mi][3],
                        as + ((wm + mi * 16 + arow) * LDS + kk + acol) * 2);
#pragma unroll
            for (int np = 0; np < 4; np++)
                ldsm_x4(rb[2 * np][0], rb[2 * np][1], rb[2 * np + 1][0], rb[2 * np + 1][1],
                        ws + ((wn + np * 16 + browl) * LDS + kk + bcoll) * 2);
#pragma unroll
            for (int mi = 0; mi < 2; mi++)
#pragma unroll
                for (int ni = 0; ni < 8; ni++)
                    asm volatile(
                        "mma.sync.aligned.m16n8k16.row.col.f32.f16.f16.f32 "
                        "{%0,%1,%2,%3}, {%4,%5,%6,%7}, {%8,%9}, {%0,%1,%2,%3};"
                        : "+f"(acc[mi][ni][0]), "+f"(acc[mi][ni][1]),
                          "+f"(acc[mi][ni][2]), "+f"(acc[mi][ni][3])
                        : "r"(ra[mi][0]), "r"(ra[mi][1]), "r"(ra[mi][2]), "r"(ra[mi][3]),
                          "r"(rb[ni][0]), "r"(rb[ni][1]));
        }
        // NOTE: no trailing barrier. Slot overwritten next iter is (i+4)%4 = i%4,
        // whose readers must have passed the NEXT top barrier first.
    }

    // ---- epilogue ----
#pragma unroll
    for (int mi = 0; mi < 2; mi++) {
#pragma unroll
        for (int ni = 0; ni < 8; ni++) {
            int r0 = brow + wm + mi * 16 + g;
            int r1 = r0 + 8;
            int c0 = bcol + wn + ni * 8 + tg * 2;
            float v0 = acc[mi][ni][0], v1 = acc[mi][ni][1];
            float v2 = acc[mi][ni][2], v3 = acc[mi][ni][3];
            float b0 = bias[c0], b1 = bias[c0 + 1];
            v0 += b0; v1 += b1; v2 += b0; v3 += b1;
            if (relu) {
                v0 = fmaxf(v0, 0.f); v1 = fmaxf(v1, 0.f);
                v2 = fmaxf(v2, 0.f); v3 = fmaxf(v3, 0.f);
            }
            if (resh) {
                float2 f0 = __half22float2(*(const __half2*)&resh[(size_t)r0 * EDIM + c0]);
                float2 f1 = __half22float2(*(const __half2*)&resh[(size_t)r1 * EDIM + c0]);
                v0 += f0.x; v1 += f0.y; v2 += f1.x; v3 += f1.y;
            }
            *(__half2*)&outh[(size_t)r0 * N + c0] = __floats2half2_rn(v0, v1);
            *(__half2*)&outh[(size_t)r1 * N + c0] = __floats2half2_rn(v2, v3);
        }
    }
}

// ------------------------- row LayerNorm (E=512, fp16 in) ---------------------
// blockIdx.y = stream. Writes fp16 (outh) and/or strided fp32 (outf col z*E).
__global__ void k_ln(LnArgs la)
{
    const int z = blockIdx.y;
    const int row = blockIdx.x;
    const int t = threadIdx.x;  // 128 threads
    const __half2* xr = (const __half2*)(la.x[z] + (size_t)row * EDIM);
    const float* gam = la.g[z];
    const float* bet = la.b[z];

    float2 v[2];
    float s = 0.f, sq = 0.f;
#pragma unroll
    for (int i = 0; i < 2; i++) {
        v[i] = __half22float2(xr[t + i * 128]);
        s  += v[i].x + v[i].y;
        sq += v[i].x * v[i].x + v[i].y * v[i].y;
    }
#pragma unroll
    for (int o = 16; o > 0; o >>= 1) {
        s  += __shfl_xor_sync(0xFFFFFFFFu, s, o);
        sq += __shfl_xor_sync(0xFFFFFFFFu, sq, o);
    }
    __shared__ float ss[4], ssq[4];
    int w = t >> 5, l = t & 31;
    if (l == 0) { ss[w] = s; ssq[w] = sq; }
    __syncthreads();
    s  = ss[0] + ss[1] + ss[2] + ss[3];
    sq = ssq[0] + ssq[1] + ssq[2] + ssq[3];
    float mean = s * (1.f / EDIM);
    float var  = sq * (1.f / EDIM) - mean * mean;
    float rstd = rsqrtf(var + 1e-5f);
#pragma unroll
    for (int i = 0; i < 2; i++) {
        int c = 2 * (t + i * 128);
        float y0 = (v[i].x - mean) * rstd * gam[c]     + bet[c];
        float y1 = (v[i].y - mean) * rstd * gam[c + 1] + bet[c + 1];
        if (la.outh[z]) *(__half2*)&la.outh[z][(size_t)row * EDIM + c] = __floats2half2_rn(y0, y1);
        if (la.outf) {
            float* o = la.outf + (size_t)row * (2 * EDIM) + z * EDIM + c;
            o[0] = y0; o[1] = y1;
        }
    }
}

// ------------------------------- launch ---------------------------------------
extern "C" void kernel_launch(void* const* d_in, const int* in_sizes, int n_in,
                              void* d_out, int out_size) {
    const float* a_in_w[2]  = { (const float*)d_in[2], (const float*)d_in[6] };
    const float* a_in_b[2]  = { (const float*)d_in[3], (const float*)d_in[7] };
    const float* a_out_w[2] = { (const float*)d_in[4], (const float*)d_in[8] };
    const float* a_out_b[2] = { (const float*)d_in[5], (const float*)d_in[9] };
    const float* lnA_g[2] = { (const float*)d_in[10], (const float*)d_in[12] };
    const float* lnA_b[2] = { (const float*)d_in[11], (const float*)d_in[13] };
    const float* lnB_g[2] = { (const float*)d_in[14], (const float*)d_in[16] };
    const float* lnB_b[2] = { (const float*)d_in[15], (const float*)d_in[17] };
    const float* f_w1[2] = { (const float*)d_in[18], (const float*)d_in[22] };
    const float* f_b1[2] = { (const float*)d_in[19], (const float*)d_in[23] };
    const float* f_w2[2] = { (const float*)d_in[20], (const float*)d_in[24] };
    const float* f_b2[2] = { (const float*)d_in[21], (const float*)d_in[25] };
    float* out = (float*)d_out;

    __half *xhb, *hb, *ub, *tb, *wcb, *w1b, *w2b;
    float* cb;
    cudaGetSymbolAddress((void**)&xhb, g_xh);
    cudaGetSymbolAddress((void**)&hb,  g_h);
    cudaGetSymbolAddress((void**)&ub,  g_u);
    cudaGetSymbolAddress((void**)&tb,  g_t);
    cudaGetSymbolAddress((void**)&wcb, g_wc);
    cudaGetSymbolAddress((void**)&cb,  g_c);
    cudaGetSymbolAddress((void**)&w1b, g_w1h);
    cudaGetSymbolAddress((void**)&w2b, g_w2h);

    __half* xh[2] = { xhb, xhb + (size_t)MROWS * EDIM };
    __half* h [2] = { hb,  hb  + (size_t)MROWS * EDIM };
    __half* u [2] = { ub,  ub  + (size_t)MROWS * FFDIM };
    __half* tt[2] = { tb,  tb  + (size_t)MROWS * EDIM };
    __half* wc[2] = { wcb, wcb + (size_t)EDIM * EDIM };
    float*  cc[2] = { cb,  cb  + EDIM };
    __half* w1[2] = { w1b, w1b + (size_t)FFDIM * EDIM };
    __half* w2[2] = { w2b, w2b + (size_t)EDIM * FFDIM };

    cudaFuncSetAttribute(k_gemm<EDIM>,
                         cudaFuncAttributeMaxDynamicSharedMemorySize, GEMM_SMEM);
    cudaFuncSetAttribute(k_gemm<FFDIM>,
                         cudaFuncAttributeMaxDynamicSharedMemorySize, GEMM_SMEM);

    const int NXE = MROWS * EDIM;
    k_f2h<<<NXE / 1024, 256>>>((const float*)d_in[0], xh[0], NXE);
    k_f2h<<<NXE / 1024, 256>>>((const float*)d_in[1], xh[1], NXE);
    for (int s = 0; s < 2; s++) {
        k_f2h<<<(FFDIM * EDIM) / 1024, 256>>>(f_w1[s], w1[s], FFDIM * EDIM);
        k_f2h<<<(EDIM * FFDIM) / 1024, 256>>>(f_w2[s], w2[s], EDIM * FFDIM);
        k_fold<<<EDIM, EDIM>>>(a_out_w[s], a_in_w[s] + 2 * EDIM * EDIM, wc[s]);
        k_foldc<<<2, 256>>>(a_out_w[s], a_out_b[s], a_in_b[s] + 2 * EDIM, cc[s]);
    }

    dim3 gE(EDIM / BN, MROWS / BM, 2);    // (4, 256, 2)
    dim3 gF(FFDIM / BN, MROWS / BM, 2);   // (8, 256, 2)
    dim3 gL(MROWS, 2);

    // t[z] = x[z] + x[1-z] @ Wc[z]^T + c[z]
    GemmArgs g1 = {{xh[1], xh[0]}, {wc[0], wc[1]}, {cc[0], cc[1]},
                   {xh[0], xh[1]}, {tt[0], tt[1]}};
    k_gemm<EDIM><<<gE, 256, GEMM_SMEM>>>(g1, EDIM, 0);

    // h[z] = LN(t[z])
    LnArgs l1 = {{tt[0], tt[1]}, {lnA_g[0], lnA_g[1]}, {lnA_b[0], lnA_b[1]},
                 {h[0], h[1]}, nullptr};
    k_ln<<<gL, 128>>>(l1);

    // u[z] = relu(h[z] @ w1[z]^T + b1[z])
    GemmArgs g2 = {{h[0], h[1]}, {w1[0], w1[1]}, {f_b1[0], f_b1[1]},
                   {nullptr, nullptr}, {u[0], u[1]}};
    k_gemm<EDIM><<<gF, 256, GEMM_SMEM>>>(g2, FFDIM, 1);

    // t[z] = h[z] + u[z] @ w2[z]^T + b2[z]
    GemmArgs g3 = {{u[0], u[1]}, {w2[0], w2[1]}, {f_b2[0], f_b2[1]},
                   {h[0], h[1]}, {tt[0], tt[1]}};
    k_gemm<FFDIM><<<gE, 256, GEMM_SMEM>>>(g3, EDIM, 0);

    // out[:, z*512:(z+1)*512] = LN(t[z])
    LnArgs l2 = {{tt[0], tt[1]}, {lnB_g[0], lnB_g[1]}, {lnB_b[0], lnB_b[1]},
                 {nullptr, nullptr}, out};
    k_ln<<<gL, 128>>>(l2);
}

// round 6
// speedup vs baseline: 1.0354x; 1.0354x over previous
#include <cuda_runtime.h>
#include <cuda_fp16.h>
#include <cstdint>
#include <cstddef>

// ----------------------------------------------------------------------------
// CrossAttention_30056181138117 on GB300 (sm_103a) — round 6
//
// (harness lowers through family-generic compute_103 PTX -> tcgen05 rejected;
// this is the tuned legacy-HMMA path)
//
// Seq-len-1 attention => softmax == 1 => attn out == V projection, folded:
//   att_s = x_other @ Wc_s^T + c_s,  Wc_s = out_w_s @ wv_s
// Per stream: h = LN(x + att); u = relu(h@w1^T+b1); o = LN(h + u@w2^T+b2)
//
// Round-6 (from round-4 winner): BK=64 (half the barriers, 2x latency cover),
// single __syncthreads per K-iter, no forced unroll, grid.z=2 stream batching.
// 3-stage cp.async, 2 CTAs/SM (108KB smem/CTA).
// ----------------------------------------------------------------------------

#define MROWS 32768
#define EDIM  512
#define FFDIM 1024

#define BM 128
#define BN 128
#define BK 64
#define NSTAGE 3
#define LDS 72                          // halfs per smem row (144B, 16B-aligned)
#define ASTG (BM * LDS)                 // halfs per A stage
#define WSTG (BN * LDS)                 // halfs per W stage
#define GEMM_SMEM (NSTAGE * (ASTG + WSTG) * 2)   // 110592 bytes

// ------------------------- device scratch (static, no allocs) ---------------
__device__ __half g_xh[2][MROWS * EDIM];
__device__ __half g_h [2][MROWS * EDIM];
__device__ __half g_u [2][MROWS * FFDIM];
__device__ __half g_t [2][MROWS * EDIM];
__device__ __half g_wc[2][EDIM * EDIM];
__device__ float  g_c [2][EDIM];
__device__ __half g_w1h[2][FFDIM * EDIM];
__device__ __half g_w2h[2][EDIM * FFDIM];

struct GemmArgs {
    const __half* A[2];
    const __half* W[2];
    const float*  bias[2];
    const __half* res[2];
    __half*       out[2];
};
struct LnArgs {
    const __half* x[2];
    const float*  g[2];
    const float*  b[2];
    __half*       outh[2];   // or null
    float*        outf;      // strided fp32 out base, or null
};

// ------------------------- helpers -------------------------------------------
__device__ __forceinline__ void cp_async16(uint32_t dst, const void* src) {
    asm volatile("cp.async.cg.shared.global [%0], [%1], 16;\n" :: "r"(dst), "l"(src));
}
__device__ __forceinline__ void ldsm_x4(uint32_t& r0, uint32_t& r1,
                                        uint32_t& r2, uint32_t& r3, uint32_t addr) {
    asm volatile("ldmatrix.sync.aligned.m8n8.x4.shared.b16 {%0,%1,%2,%3}, [%4];"
                 : "=r"(r0), "=r"(r1), "=r"(r2), "=r"(r3) : "r"(addr));
}

// ------------------------- small kernels -------------------------------------
__global__ void k_f2h(const float* __restrict__ src, __half* __restrict__ dst, int n) {
    int i = (blockIdx.x * blockDim.x + threadIdx.x) * 4;
    if (i >= n) return;
    float4 v = *(const float4*)(src + i);
    __half2* d = (__half2*)(dst + i);
    d[0] = __floats2half2_rn(v.x, v.y);
    d[1] = __floats2half2_rn(v.z, v.w);
}

__global__ void k_fold(const float* __restrict__ out_w,
                       const float* __restrict__ wv,
                       __half* __restrict__ wc) {
    __shared__ float srow[EDIM];
    int i = blockIdx.x, k = threadIdx.x;
    srow[k] = out_w[i * EDIM + k];
    __syncthreads();
    float acc = 0.f;
#pragma unroll 4
    for (int j = 0; j < EDIM; j++) acc = fmaf(srow[j], wv[j * EDIM + k], acc);
    wc[i * EDIM + k] = __float2half(acc);
}

__global__ void k_foldc(const float* __restrict__ out_w,
                        const float* __restrict__ out_b,
                        const float* __restrict__ bv,
                        float* __restrict__ c) {
    int i = blockIdx.x * blockDim.x + threadIdx.x;
    if (i >= EDIM) return;
    float acc = out_b[i];
    for (int j = 0; j < EDIM; j++) acc = fmaf(out_w[i * EDIM + j], bv[j], acc);
    c[i] = acc;
}

// ------------------------- fp16 HMMA GEMM -------------------------------------
// z = blockIdx.z selects the stream. out[r][n] = sum_k A[r][k]*W[n][k]
// (+bias, opt relu, opt fp16 residual) -> fp16
template <int K>
__global__ __launch_bounds__(256, 2) void k_gemm(GemmArgs ga, int N, int relu)
{
    constexpr int NT = K / BK;             // 8 or 16
    const int z = blockIdx.z;
    const __half* __restrict__ A    = ga.A[z];
    const __half* __restrict__ W    = ga.W[z];
    const float*  __restrict__ bias = ga.bias[z];
    const __half* __restrict__ resh = ga.res[z];
    __half*       __restrict__ outh = ga.out[z];

    extern __shared__ __half smem[];
    __half* Asm = smem;
    __half* Wsm = smem + NSTAGE * ASTG;
    const uint32_t as_u = (uint32_t)__cvta_generic_to_shared(Asm);
    const uint32_t ws_u = (uint32_t)__cvta_generic_to_shared(Wsm);

    const int t = threadIdx.x;
    const int warp = t >> 5, lane = t & 31;
    const int g = lane >> 2, tg = lane & 3;
    const int brow = blockIdx.y * BM;
    const int bcol = blockIdx.x * BN;
    const int wm = (warp >> 1) * 32;
    const int wn = (warp & 1) * 64;

    // load mapping: per operand 128 rows x 8 col16; idx = t + i*256;
    // row = idx>>3, col16 = idx&7  (4 iterations per operand)
    const int lrow = t >> 3;          // base row 0..31
    const int lc16 = t & 7;           // 16B column 0..7
    const __half* Ag = A + (size_t)(brow + lrow) * K + lc16 * 8;
    const __half* Wg = W + (size_t)(bcol + lrow) * K + lc16 * 8;

    // ldmatrix lane roles
    const int arow = lane & 15;
    const int acol = (lane & 16) >> 1;
    const int browl = (lane & 7) + ((lane & 16) >> 1);
    const int bcoll = lane & 8;

    float acc[2][8][4];
#pragma unroll
    for (int a = 0; a < 2; a++)
#pragma unroll
        for (int b = 0; b < 8; b++)
#pragma unroll
            for (int c = 0; c < 4; c++) acc[a][b][c] = 0.f;

    auto load_stage = [&](int i, int slot) {
        const int ko = i * BK;
        const uint32_t as = as_u + (slot * ASTG + lrow * LDS + lc16 * 8) * 2;
        const uint32_t ws = ws_u + (slot * WSTG + lrow * LDS + lc16 * 8) * 2;
#pragma unroll
        for (int r = 0; r < 4; r++) {
            cp_async16(as + r * 32 * LDS * 2, Ag + ko + (size_t)(r * 32) * K);
            cp_async16(ws + r * 32 * LDS * 2, Wg + ko + (size_t)(r * 32) * K);
        }
        asm volatile("cp.async.commit_group;\n");
    };

    // prologue: fill 2 of 3 slots
    load_stage(0, 0);
    load_stage(1, 1);

    for (int i = 0; i < NT; i++) {
        if (i + 1 < NT) asm volatile("cp.async.wait_group 1;\n");
        else            asm volatile("cp.async.wait_group 0;\n");
        __syncthreads();   // single barrier per K-iter

        if (i + 2 < NT) load_stage(i + 2, (i + 2) % NSTAGE);

        const int s = i % NSTAGE;
        const uint32_t as = as_u + s * ASTG * 2;
        const uint32_t ws = ws_u + s * WSTG * 2;

#pragma unroll
        for (int kk = 0; kk < BK; kk += 16) {
            uint32_t ra[2][4], rb[8][2];
#pragma unroll
            for (int mi = 0; mi < 2; mi++)
                ldsm_x4(ra[mi][0], ra[mi][1], ra[mi][2], ra[mi][3],
                        as + ((wm + mi * 16 + arow) * LDS + kk + acol) * 2);
#pragma unroll
            for (int np = 0; np < 4; np++)
                ldsm_x4(rb[2 * np][0], rb[2 * np][1], rb[2 * np + 1][0], rb[2 * np + 1][1],
                        ws + ((wn + np * 16 + browl) * LDS + kk + bcoll) * 2);
#pragma unroll
            for (int mi = 0; mi < 2; mi++)
#pragma unroll
                for (int ni = 0; ni < 8; ni++)
                    asm volatile(
                        "mma.sync.aligned.m16n8k16.row.col.f32.f16.f16.f32 "
                        "{%0,%1,%2,%3}, {%4,%5,%6,%7}, {%8,%9}, {%0,%1,%2,%3};"
                        : "+f"(acc[mi][ni][0]), "+f"(acc[mi][ni][1]),
                          "+f"(acc[mi][ni][2]), "+f"(acc[mi][ni][3])
                        : "r"(ra[mi][0]), "r"(ra[mi][1]), "r"(ra[mi][2]), "r"(ra[mi][3]),
                          "r"(rb[ni][0]), "r"(rb[ni][1]));
        }
        // no trailing barrier: next iter's prefetch writes slot (i+2)%3 == (i-1)%3,
        // whose readers all passed this iter's top barrier already.
    }

    // ---- epilogue ----
#pragma unroll
    for (int mi = 0; mi < 2; mi++) {
#pragma unroll
        for (int ni = 0; ni < 8; ni++) {
            int r0 = brow + wm + mi * 16 + g;
            int r1 = r0 + 8;
            int c0 = bcol + wn + ni * 8 + tg * 2;
            float v0 = acc[mi][ni][0], v1 = acc[mi][ni][1];
            float v2 = acc[mi][ni][2], v3 = acc[mi][ni][3];
            float b0 = bias[c0], b1 = bias[c0 + 1];
            v0 += b0; v1 += b1; v2 += b0; v3 += b1;
            if (relu) {
                v0 = fmaxf(v0, 0.f); v1 = fmaxf(v1, 0.f);
                v2 = fmaxf(v2, 0.f); v3 = fmaxf(v3, 0.f);
            }
            if (resh) {
                float2 f0 = __half22float2(*(const __half2*)&resh[(size_t)r0 * EDIM + c0]);
                float2 f1 = __half22float2(*(const __half2*)&resh[(size_t)r1 * EDIM + c0]);
                v0 += f0.x; v1 += f0.y; v2 += f1.x; v3 += f1.y;
            }
            *(__half2*)&outh[(size_t)r0 * N + c0] = __floats2half2_rn(v0, v1);
            *(__half2*)&outh[(size_t)r1 * N + c0] = __floats2half2_rn(v2, v3);
        }
    }
}

// ------------------------- row LayerNorm (E=512, fp16 in) ---------------------
__global__ void k_ln(LnArgs la)
{
    const int z = blockIdx.y;
    const int row = blockIdx.x;
    const int t = threadIdx.x;  // 128 threads
    const __half2* xr = (const __half2*)(la.x[z] + (size_t)row * EDIM);
    const float* gam = la.g[z];
    const float* bet = la.b[z];

    float2 v[2];
    float s = 0.f, sq = 0.f;
#pragma unroll
    for (int i = 0; i < 2; i++) {
        v[i] = __half22float2(xr[t + i * 128]);
        s  += v[i].x + v[i].y;
        sq += v[i].x * v[i].x + v[i].y * v[i].y;
    }
#pragma unroll
    for (int o = 16; o > 0; o >>= 1) {
        s  += __shfl_xor_sync(0xFFFFFFFFu, s, o);
        sq += __shfl_xor_sync(0xFFFFFFFFu, sq, o);
    }
    __shared__ float ss[4], ssq[4];
    int w = t >> 5, l = t & 31;
    if (l == 0) { ss[w] = s; ssq[w] = sq; }
    __syncthreads();
    s  = ss[0] + ss[1] + ss[2] + ss[3];
    sq = ssq[0] + ssq[1] + ssq[2] + ssq[3];
    float mean = s * (1.f / EDIM);
    float var  = sq * (1.f / EDIM) - mean * mean;
    float rstd = rsqrtf(var + 1e-5f);
#pragma unroll
    for (int i = 0; i < 2; i++) {
        int c = 2 * (t + i * 128);
        float y0 = (v[i].x - mean) * rstd * gam[c]     + bet[c];
        float y1 = (v[i].y - mean) * rstd * gam[c + 1] + bet[c + 1];
        if (la.outh[z]) *(__half2*)&la.outh[z][(size_t)row * EDIM + c] = __floats2half2_rn(y0, y1);
        if (la.outf) {
            float* o = la.outf + (size_t)row * (2 * EDIM) + z * EDIM + c;
            o[0] = y0; o[1] = y1;
        }
    }
}

// ------------------------------- launch ---------------------------------------
extern "C" void kernel_launch(void* const* d_in, const int* in_sizes, int n_in,
                              void* d_out, int out_size) {
    const float* a_in_w[2]  = { (const float*)d_in[2], (const float*)d_in[6] };
    const float* a_in_b[2]  = { (const float*)d_in[3], (const float*)d_in[7] };
    const float* a_out_w[2] = { (const float*)d_in[4], (const float*)d_in[8] };
    const float* a_out_b[2] = { (const float*)d_in[5], (const float*)d_in[9] };
    const float* lnA_g[2] = { (const float*)d_in[10], (const float*)d_in[12] };
    const float* lnA_b[2] = { (const float*)d_in[11], (const float*)d_in[13] };
    const float* lnB_g[2] = { (const float*)d_in[14], (const float*)d_in[16] };
    const float* lnB_b[2] = { (const float*)d_in[15], (const float*)d_in[17] };
    const float* f_w1[2] = { (const float*)d_in[18], (const float*)d_in[22] };
    const float* f_b1[2] = { (const float*)d_in[19], (const float*)d_in[23] };
    const float* f_w2[2] = { (const float*)d_in[20], (const float*)d_in[24] };
    const float* f_b2[2] = { (const float*)d_in[21], (const float*)d_in[25] };
    float* out = (float*)d_out;

    __half *xhb, *hb, *ub, *tb, *wcb, *w1b, *w2b;
    float* cb;
    cudaGetSymbolAddress((void**)&xhb, g_xh);
    cudaGetSymbolAddress((void**)&hb,  g_h);
    cudaGetSymbolAddress((void**)&ub,  g_u);
    cudaGetSymbolAddress((void**)&tb,  g_t);
    cudaGetSymbolAddress((void**)&wcb, g_wc);
    cudaGetSymbolAddress((void**)&cb,  g_c);
    cudaGetSymbolAddress((void**)&w1b, g_w1h);
    cudaGetSymbolAddress((void**)&w2b, g_w2h);

    __half* xh[2] = { xhb, xhb + (size_t)MROWS * EDIM };
    __half* h [2] = { hb,  hb  + (size_t)MROWS * EDIM };
    __half* u [2] = { ub,  ub  + (size_t)MROWS * FFDIM };
    __half* tt[2] = { tb,  tb  + (size_t)MROWS * EDIM };
    __half* wc[2] = { wcb, wcb + (size_t)EDIM * EDIM };
    float*  cc[2] = { cb,  cb  + EDIM };
    __half* w1[2] = { w1b, w1b + (size_t)FFDIM * EDIM };
    __half* w2[2] = { w2b, w2b + (size_t)EDIM * FFDIM };

    cudaFuncSetAttribute(k_gemm<EDIM>,
                         cudaFuncAttributeMaxDynamicSharedMemorySize, GEMM_SMEM);
    cudaFuncSetAttribute(k_gemm<FFDIM>,
                         cudaFuncAttributeMaxDynamicSharedMemorySize, GEMM_SMEM);

    const int NXE = MROWS * EDIM;
    k_f2h<<<NXE / 1024, 256>>>((const float*)d_in[0], xh[0], NXE);
    k_f2h<<<NXE / 1024, 256>>>((const float*)d_in[1], xh[1], NXE);
    for (int s = 0; s < 2; s++) {
        k_f2h<<<(FFDIM * EDIM) / 1024, 256>>>(f_w1[s], w1[s], FFDIM * EDIM);
        k_f2h<<<(EDIM * FFDIM) / 1024, 256>>>(f_w2[s], w2[s], EDIM * FFDIM);
        k_fold<<<EDIM, EDIM>>>(a_out_w[s], a_in_w[s] + 2 * EDIM * EDIM, wc[s]);
        k_foldc<<<2, 256>>>(a_out_w[s], a_out_b[s], a_in_b[s] + 2 * EDIM, cc[s]);
    }

    dim3 gE(EDIM / BN, MROWS / BM, 2);    // (4, 256, 2)
    dim3 gF(FFDIM / BN, MROWS / BM, 2);   // (8, 256, 2)
    dim3 gL(MROWS, 2);

    // t[z] = x[z] + x[1-z] @ Wc[z]^T + c[z]
    GemmArgs g1 = {{xh[1], xh[0]}, {wc[0], wc[1]}, {cc[0], cc[1]},
                   {xh[0], xh[1]}, {tt[0], tt[1]}};
    k_gemm<EDIM><<<gE, 256, GEMM_SMEM>>>(g1, EDIM, 0);

    // h[z] = LN(t[z])
    LnArgs l1 = {{tt[0], tt[1]}, {lnA_g[0], lnA_g[1]}, {lnA_b[0], lnA_b[1]},
                 {h[0], h[1]}, nullptr};
    k_ln<<<gL, 128>>>(l1);

    // u[z] = relu(h[z] @ w1[z]^T + b1[z])
    GemmArgs g2 = {{h[0], h[1]}, {w1[0], w1[1]}, {f_b1[0], f_b1[1]},
                   {nullptr, nullptr}, {u[0], u[1]}};
    k_gemm<EDIM><<<gF, 256, GEMM_SMEM>>>(g2, FFDIM, 1);

    // t[z] = h[z] + u[z] @ w2[z]^T + b2[z]
    GemmArgs g3 = {{u[0], u[1]}, {w2[0], w2[1]}, {f_b2[0], f_b2[1]},
                   {h[0], h[1]}, {tt[0], tt[1]}};
    k_gemm<FFDIM><<<gE, 256, GEMM_SMEM>>>(g3, EDIM, 0);

    // out[:, z*512:(z+1)*512] = LN(t[z])
    LnArgs l2 = {{tt[0], tt[1]}, {lnB_g[0], lnB_g[1]}, {lnB_b[0], lnB_b[1]},
                 {nullptr, nullptr}, out};
    k_ln<<<gL, 128>>>(l2);
}

// round 7
// speedup vs baseline: 1.1229x; 1.0845x over previous
#include <cuda_runtime.h>
#include <cuda_fp16.h>
#include <cstdint>

// ----------------------------------------------------------------------------
// CrossAttention_30056181138117 on GB300 (sm_103a) — round 7
//
// (harness lowers through family-generic compute_103 PTX -> tcgen05 rejected;
// tuned legacy-HMMA path)
//
// Seq-len-1 attention => softmax == 1 => attn out == V projection, folded:
//   att_s = x_other @ Wc_s^T + c_s,  Wc_s = out_w_s @ wv_s
// Per stream: h = LN(x + att); u = relu(h@w1^T+b1); o = LN(h + u@w2^T+b2)
//
// Round-7 = round-4 winner (992us) with EXACTLY ONE change: the trailing
// __syncthreads per K-iter is removed (safe: the slot overwritten by the
// iter-(i+1) prefetch was fully consumed before the iter-(i+1) top barrier).
// grid.z batching from rounds 5/6 is reverted (L2-thrash regressor).
// ----------------------------------------------------------------------------

#define MROWS 32768
#define EDIM  512
#define FFDIM 1024

#define BM 128
#define BN 128
#define BK 32
#define NSTAGE 3
#define LDS 40                          // halfs per smem row (80B, 16B-aligned)
#define ASTG (BM * LDS)                 // halfs per A stage
#define WSTG (BN * LDS)                 // halfs per W stage
#define GEMM_SMEM (NSTAGE * (ASTG + WSTG) * 2)   // 61440 bytes

// ------------------------- device scratch (static, no allocs) ---------------
__device__ __half g_xh0[MROWS * EDIM];
__device__ __half g_xh1[MROWS * EDIM];
__device__ __half g_h  [MROWS * EDIM];
__device__ __half g_u  [MROWS * FFDIM];
__device__ __half g_t16[MROWS * EDIM];
__device__ __half g_wc [2 * EDIM * EDIM];
__device__ float  g_c  [2 * EDIM];
__device__ __half g_w1h[2 * FFDIM * EDIM];
__device__ __half g_w2h[2 * EDIM * FFDIM];

// ------------------------- helpers -------------------------------------------
__device__ __forceinline__ void cp_async16(uint32_t dst, const void* src) {
    asm volatile("cp.async.cg.shared.global [%0], [%1], 16;\n" :: "r"(dst), "l"(src));
}
__device__ __forceinline__ void ldsm_x4(uint32_t& r0, uint32_t& r1,
                                        uint32_t& r2, uint32_t& r3, uint32_t addr) {
    asm volatile("ldmatrix.sync.aligned.m8n8.x4.shared.b16 {%0,%1,%2,%3}, [%4];"
                 : "=r"(r0), "=r"(r1), "=r"(r2), "=r"(r3) : "r"(addr));
}

// ------------------------- small kernels -------------------------------------
__global__ void k_f2h(const float* __restrict__ src, __half* __restrict__ dst, int n) {
    int i = (blockIdx.x * blockDim.x + threadIdx.x) * 4;
    if (i >= n) return;
    float4 v = *(const float4*)(src + i);
    __half2* d = (__half2*)(dst + i);
    d[0] = __floats2half2_rn(v.x, v.y);
    d[1] = __floats2half2_rn(v.z, v.w);
}

__global__ void k_fold(const float* __restrict__ out_w,
                       const float* __restrict__ wv,
                       __half* __restrict__ wc) {
    __shared__ float srow[EDIM];
    int i = blockIdx.x, k = threadIdx.x;
    srow[k] = out_w[i * EDIM + k];
    __syncthreads();
    float acc = 0.f;
#pragma unroll 4
    for (int j = 0; j < EDIM; j++) acc = fmaf(srow[j], wv[j * EDIM + k], acc);
    wc[i * EDIM + k] = __float2half(acc);
}

__global__ void k_foldc(const float* __restrict__ out_w,
                        const float* __restrict__ out_b,
                        const float* __restrict__ bv,
                        float* __restrict__ c) {
    int i = blockIdx.x * blockDim.x + threadIdx.x;
    if (i >= EDIM) return;
    float acc = out_b[i];
    for (int j = 0; j < EDIM; j++) acc = fmaf(out_w[i * EDIM + j], bv[j], acc);
    c[i] = acc;
}

// ------------------------- fp16 HMMA GEMM -------------------------------------
// out[r][n] = sum_k A[r][k]*W[n][k] (+bias, opt relu, opt fp16 residual) -> fp16
template <int K>
__global__ __launch_bounds__(256, 2) void k_gemm(
    const __half* __restrict__ A, const __half* __restrict__ W,
    const float* __restrict__ bias,
    const __half* __restrict__ resh,   // fp16 residual [M, EDIM] or null
    __half* __restrict__ outh,         // fp16 out [M, N]
    int N, int relu)
{
    constexpr int NT = K / BK;
    extern __shared__ __half smem[];
    __half* Asm = smem;
    __half* Wsm = smem + NSTAGE * ASTG;
    const uint32_t as_u = (uint32_t)__cvta_generic_to_shared(Asm);
    const uint32_t ws_u = (uint32_t)__cvta_generic_to_shared(Wsm);

    const int t = threadIdx.x;
    const int warp = t >> 5, lane = t & 31;
    const int g = lane >> 2, tg = lane & 3;
    const int brow = blockIdx.y * BM;
    const int bcol = blockIdx.x * BN;
    const int wm = (warp >> 1) * 32;
    const int wn = (warp & 1) * 64;

    const int lr = t >> 2;
    const int lc = (t & 3) * 8;
    const __half* Ag = A + (size_t)(brow + lr) * K + lc;
    const __half* Wg = W + (size_t)(bcol + lr) * K + lc;

    const int arow = lane & 15;
    const int acol = (lane & 16) >> 1;
    const int browl = (lane & 7) + ((lane & 16) >> 1);
    const int bcoll = lane & 8;

    float acc[2][8][4];
#pragma unroll
    for (int a = 0; a < 2; a++)
#pragma unroll
        for (int b = 0; b < 8; b++)
#pragma unroll
            for (int c = 0; c < 4; c++) acc[a][b][c] = 0.f;

    auto load_stage = [&](int i, int slot) {
        const int ko = i * BK;
        const uint32_t as = as_u + slot * ASTG * 2;
        const uint32_t ws = ws_u + slot * WSTG * 2;
        cp_async16(as + (lr * LDS + lc) * 2,        Ag + ko);
        cp_async16(as + ((lr + 64) * LDS + lc) * 2, Ag + ko + (size_t)64 * K);
        cp_async16(ws + (lr * LDS + lc) * 2,        Wg + ko);
        cp_async16(ws + ((lr + 64) * LDS + lc) * 2, Wg + ko + (size_t)64 * K);
        asm volatile("cp.async.commit_group;\n");
    };

    load_stage(0, 0);
    load_stage(1, 1);

    for (int i = 0; i < NT; i++) {
        if (i + 1 < NT) asm volatile("cp.async.wait_group 1;\n");
        else            asm volatile("cp.async.wait_group 0;\n");
        __syncthreads();   // single barrier per K-iter

        if (i + 2 < NT) load_stage(i + 2, (i + 2) % NSTAGE);

        const int s = i % NSTAGE;
        const uint32_t as = as_u + s * ASTG * 2;
        const uint32_t ws = ws_u + s * WSTG * 2;

#pragma unroll
        for (int kk = 0; kk < BK; kk += 16) {
            uint32_t ra[2][4], rb[8][2];
#pragma unroll
            for (int mi = 0; mi < 2; mi++)
                ldsm_x4(ra[mi][0], ra[mi][1], ra[mi][2], ra[mi][3],
                        as + ((wm + mi * 16 + arow) * LDS + kk + acol) * 2);
#pragma unroll
            for (int np = 0; np < 4; np++)
                ldsm_x4(rb[2 * np][0], rb[2 * np][1], rb[2 * np + 1][0], rb[2 * np + 1][1],
                        ws + ((wn + np * 16 + browl) * LDS + kk + bcoll) * 2);
#pragma unroll
            for (int mi = 0; mi < 2; mi++)
#pragma unroll
                for (int ni = 0; ni < 8; ni++)
                    asm volatile(
                        "mma.sync.aligned.m16n8k16.row.col.f32.f16.f16.f32 "
                        "{%0,%1,%2,%3}, {%4,%5,%6,%7}, {%8,%9}, {%0,%1,%2,%3};"
                        : "+f"(acc[mi][ni][0]), "+f"(acc[mi][ni][1]),
                          "+f"(acc[mi][ni][2]), "+f"(acc[mi][ni][3])
                        : "r"(ra[mi][0]), "r"(ra[mi][1]), "r"(ra[mi][2]), "r"(ra[mi][3]),
                          "r"(rb[ni][0]), "r"(rb[ni][1]));
        }
        // no trailing barrier: iter-(i+1) prefetch writes slot (i+3)%3 == i%3,
        // whose readers all passed the iter-(i+1) top barrier after finishing
        // this iteration's compute.
    }

    // ---- epilogue ----
#pragma unroll
    for (int mi = 0; mi < 2; mi++) {
#pragma unroll
        for (int ni = 0; ni < 8; ni++) {
            int r0 = brow + wm + mi * 16 + g;
            int r1 = r0 + 8;
            int c0 = bcol + wn + ni * 8 + tg * 2;
            float v0 = acc[mi][ni][0], v1 = acc[mi][ni][1];
            float v2 = acc[mi][ni][2], v3 = acc[mi][ni][3];
            float b0 = bias[c0], b1 = bias[c0 + 1];
            v0 += b0; v1 += b1; v2 += b0; v3 += b1;
            if (relu) {
                v0 = fmaxf(v0, 0.f); v1 = fmaxf(v1, 0.f);
                v2 = fmaxf(v2, 0.f); v3 = fmaxf(v3, 0.f);
            }
            if (resh) {
                float2 f0 = __half22float2(*(const __half2*)&resh[(size_t)r0 * EDIM + c0]);
                float2 f1 = __half22float2(*(const __half2*)&resh[(size_t)r1 * EDIM + c0]);
                v0 += f0.x; v1 += f0.y; v2 += f1.x; v3 += f1.y;
            }
            *(__half2*)&outh[(size_t)r0 * N + c0] = __floats2half2_rn(v0, v1);
            *(__half2*)&outh[(size_t)r1 * N + c0] = __floats2half2_rn(v2, v3);
        }
    }
}

// ------------------------- row LayerNorm (E=512, fp16 in) ---------------------
__global__ void k_ln(const __half* __restrict__ x,
                     const float* __restrict__ gam, const float* __restrict__ bet,
                     __half* __restrict__ outh, float* __restrict__ outf,
                     int ld_out, int coloff)
{
    int row = blockIdx.x;
    int t = threadIdx.x;  // 128 threads
    const __half2* xr = (const __half2*)(x + (size_t)row * EDIM);
    float2 v[2];
    float s = 0.f, sq = 0.f;
#pragma unroll
    for (int i = 0; i < 2; i++) {
        v[i] = __half22float2(xr[t + i * 128]);
        s  += v[i].x + v[i].y;
        sq += v[i].x * v[i].x + v[i].y * v[i].y;
    }
#pragma unroll
    for (int o = 16; o > 0; o >>= 1) {
        s  += __shfl_xor_sync(0xFFFFFFFFu, s, o);
        sq += __shfl_xor_sync(0xFFFFFFFFu, sq, o);
    }
    __shared__ float ss[4], ssq[4];
    int w = t >> 5, l = t & 31;
    if (l == 0) { ss[w] = s; ssq[w] = sq; }
    __syncthreads();
    s  = ss[0] + ss[1] + ss[2] + ss[3];
    sq = ssq[0] + ssq[1] + ssq[2] + ssq[3];
    float mean = s * (1.f / EDIM);
    float var  = sq * (1.f / EDIM) - mean * mean;
    float rstd = rsqrtf(var + 1e-5f);
#pragma unroll
    for (int i = 0; i < 2; i++) {
        int c = 2 * (t + i * 128);
        float y0 = (v[i].x - mean) * rstd * gam[c]     + bet[c];
        float y1 = (v[i].y - mean) * rstd * gam[c + 1] + bet[c + 1];
        if (outh) *(__half2*)&outh[(size_t)row * EDIM + c] = __floats2half2_rn(y0, y1);
        if (outf) {
            outf[(size_t)row * ld_out + coloff + c]     = y0;
            outf[(size_t)row * ld_out + coloff + c + 1] = y1;
        }
    }
}

// ------------------------------- launch ---------------------------------------
extern "C" void kernel_launch(void* const* d_in, const int* in_sizes, int n_in,
                              void* d_out, int out_size) {
    const float* a_in_w[2]  = { (const float*)d_in[2], (const float*)d_in[6] };
    const float* a_in_b[2]  = { (const float*)d_in[3], (const float*)d_in[7] };
    const float* a_out_w[2] = { (const float*)d_in[4], (const float*)d_in[8] };
    const float* a_out_b[2] = { (const float*)d_in[5], (const float*)d_in[9] };
    const float* lnA_g[2] = { (const float*)d_in[10], (const float*)d_in[12] };
    const float* lnA_b[2] = { (const float*)d_in[11], (const float*)d_in[13] };
    const float* lnB_g[2] = { (const float*)d_in[14], (const float*)d_in[16] };
    const float* lnB_b[2] = { (const float*)d_in[15], (const float*)d_in[17] };
    const float* f_w1[2] = { (const float*)d_in[18], (const float*)d_in[22] };
    const float* f_b1[2] = { (const float*)d_in[19], (const float*)d_in[23] };
    const float* f_w2[2] = { (const float*)d_in[20], (const float*)d_in[24] };
    const float* f_b2[2] = { (const float*)d_in[21], (const float*)d_in[25] };
    float* out = (float*)d_out;

    __half *xh[2], *hbuf, *ubuf, *t16, *wc, *w1h, *w2h;
    float *cbuf;
    cudaGetSymbolAddress((void**)&xh[0], g_xh0);
    cudaGetSymbolAddress((void**)&xh[1], g_xh1);
    cudaGetSymbolAddress((void**)&hbuf, g_h);
    cudaGetSymbolAddress((void**)&ubuf, g_u);
    cudaGetSymbolAddress((void**)&t16,  g_t16);
    cudaGetSymbolAddress((void**)&wc,   g_wc);
    cudaGetSymbolAddress((void**)&cbuf, g_c);
    cudaGetSymbolAddress((void**)&w1h,  g_w1h);
    cudaGetSymbolAddress((void**)&w2h,  g_w2h);

    cudaFuncSetAttribute(k_gemm<EDIM>,
                         cudaFuncAttributeMaxDynamicSharedMemorySize, GEMM_SMEM);
    cudaFuncSetAttribute(k_gemm<FFDIM>,
                         cudaFuncAttributeMaxDynamicSharedMemorySize, GEMM_SMEM);

    const int NXE = MROWS * EDIM;
    k_f2h<<<NXE / 1024, 256>>>((const float*)d_in[0], xh[0], NXE);
    k_f2h<<<NXE / 1024, 256>>>((const float*)d_in[1], xh[1], NXE);
    for (int s = 0; s < 2; s++) {
        k_f2h<<<(FFDIM * EDIM) / 1024, 256>>>(f_w1[s], w1h + (size_t)s * FFDIM * EDIM, FFDIM * EDIM);
        k_f2h<<<(EDIM * FFDIM) / 1024, 256>>>(f_w2[s], w2h + (size_t)s * EDIM * FFDIM, EDIM * FFDIM);
        k_fold<<<EDIM, EDIM>>>(a_out_w[s], a_in_w[s] + 2 * EDIM * EDIM, wc + (size_t)s * EDIM * EDIM);
        k_foldc<<<2, 256>>>(a_out_w[s], a_out_b[s], a_in_b[s] + 2 * EDIM, cbuf + s * EDIM);
    }

    dim3 gE(EDIM / BN, MROWS / BM);    // (4, 256)
    dim3 gF(FFDIM / BN, MROWS / BM);   // (8, 256)

    for (int s = 0; s < 2; s++) {
        const __half* kv = xh[1 - s];

        // t = x_s + kv @ Wc^T + c
        k_gemm<EDIM><<<gE, 256, GEMM_SMEM>>>(kv, wc + (size_t)s * EDIM * EDIM,
                                             cbuf + s * EDIM, xh[s], t16, EDIM, 0);
        // h = LN(t)
        k_ln<<<MROWS, 128>>>(t16, lnA_g[s], lnA_b[s], hbuf, nullptr, 0, 0);
        // u = relu(h @ w1^T + b1)
        k_gemm<EDIM><<<gF, 256, GEMM_SMEM>>>(hbuf, w1h + (size_t)s * FFDIM * EDIM,
                                             f_b1[s], nullptr, ubuf, FFDIM, 1);
        // t = h + u @ w2^T + b2
        k_gemm<FFDIM><<<gE, 256, GEMM_SMEM>>>(ubuf, w2h + (size_t)s * EDIM * FFDIM,
                                              f_b2[s], hbuf, t16, EDIM, 0);
        // out[:, s*512 : (s+1)*512] = LN(t)
        k_ln<<<MROWS, 128>>>(t16, lnB_g[s], lnB_b[s], nullptr, out, 2 * EDIM, s * EDIM);
    }
}

// round 8
// speedup vs baseline: 1.3888x; 1.2368x over previous
#include <cuda_runtime.h>
#include <cuda_fp16.h>
#include <cstdint>

// ----------------------------------------------------------------------------
// CrossAttention_30056181138117 on GB300 (sm_103a) — round 8
//
// (harness lowers through family-generic compute_103 PTX -> tcgen05 rejected;
// tuned legacy-HMMA path)
//
// Seq-len-1 attention => softmax == 1 => attn out == V projection, folded:
//   att_s = x_other @ Wc_s^T + c_s,  Wc_s = out_w_s @ wv_s
// Per stream: h = LN(x + att); u = relu(h@w1^T+b1); o = LN(h + u@w2^T+b2)
//
// Round-8 = round-7 winner (969us) with ONE structural change: the two
// independent per-stream pipelines run on forked capture streams
// (event fork/join), with per-stream private scratch buffers, so each
// branch's LN/convert/fold work and GEMM tail waves hide under the other
// branch's GEMMs. GEMM/LN kernels byte-identical to round 7.
// ----------------------------------------------------------------------------

#define MROWS 32768
#define EDIM  512
#define FFDIM 1024

#define BM 128
#define BN 128
#define BK 32
#define NSTAGE 3
#define LDS 40                          // halfs per smem row (80B, 16B-aligned)
#define ASTG (BM * LDS)
#define WSTG (BN * LDS)
#define GEMM_SMEM (NSTAGE * (ASTG + WSTG) * 2)   // 61440 bytes

// ------------------------- device scratch (static, no allocs) ---------------
__device__ __half g_xh0[MROWS * EDIM];
__device__ __half g_xh1[MROWS * EDIM];
__device__ __half g_h  [2][MROWS * EDIM];
__device__ __half g_u  [2][MROWS * FFDIM];
__device__ __half g_t16[2][MROWS * EDIM];
__device__ __half g_wc [2 * EDIM * EDIM];
__device__ float  g_c  [2 * EDIM];
__device__ __half g_w1h[2 * FFDIM * EDIM];
__device__ __half g_w2h[2 * EDIM * FFDIM];

// ------------------------- helpers -------------------------------------------
__device__ __forceinline__ void cp_async16(uint32_t dst, const void* src) {
    asm volatile("cp.async.cg.shared.global [%0], [%1], 16;\n" :: "r"(dst), "l"(src));
}
__device__ __forceinline__ void ldsm_x4(uint32_t& r0, uint32_t& r1,
                                        uint32_t& r2, uint32_t& r3, uint32_t addr) {
    asm volatile("ldmatrix.sync.aligned.m8n8.x4.shared.b16 {%0,%1,%2,%3}, [%4];"
                 : "=r"(r0), "=r"(r1), "=r"(r2), "=r"(r3) : "r"(addr));
}

// ------------------------- small kernels -------------------------------------
__global__ void k_f2h(const float* __restrict__ src, __half* __restrict__ dst, int n) {
    int i = (blockIdx.x * blockDim.x + threadIdx.x) * 4;
    if (i >= n) return;
    float4 v = *(const float4*)(src + i);
    __half2* d = (__half2*)(dst + i);
    d[0] = __floats2half2_rn(v.x, v.y);
    d[1] = __floats2half2_rn(v.z, v.w);
}

__global__ void k_fold(const float* __restrict__ out_w,
                       const float* __restrict__ wv,
                       __half* __restrict__ wc) {
    __shared__ float srow[EDIM];
    int i = blockIdx.x, k = threadIdx.x;
    srow[k] = out_w[i * EDIM + k];
    __syncthreads();
    float acc = 0.f;
#pragma unroll 4
    for (int j = 0; j < EDIM; j++) acc = fmaf(srow[j], wv[j * EDIM + k], acc);
    wc[i * EDIM + k] = __float2half(acc);
}

__global__ void k_foldc(const float* __restrict__ out_w,
                        const float* __restrict__ out_b,
                        const float* __restrict__ bv,
                        float* __restrict__ c) {
    int i = blockIdx.x * blockDim.x + threadIdx.x;
    if (i >= EDIM) return;
    float acc = out_b[i];
    for (int j = 0; j < EDIM; j++) acc = fmaf(out_w[i * EDIM + j], bv[j], acc);
    c[i] = acc;
}

// ------------------------- fp16 HMMA GEMM (identical to round 7) --------------
template <int K>
__global__ __launch_bounds__(256, 2) void k_gemm(
    const __half* __restrict__ A, const __half* __restrict__ W,
    const float* __restrict__ bias,
    const __half* __restrict__ resh,
    __half* __restrict__ outh,
    int N, int relu)
{
    constexpr int NT = K / BK;
    extern __shared__ __half smem[];
    __half* Asm = smem;
    __half* Wsm = smem + NSTAGE * ASTG;
    const uint32_t as_u = (uint32_t)__cvta_generic_to_shared(Asm);
    const uint32_t ws_u = (uint32_t)__cvta_generic_to_shared(Wsm);

    const int t = threadIdx.x;
    const int warp = t >> 5, lane = t & 31;
    const int g = lane >> 2, tg = lane & 3;
    const int brow = blockIdx.y * BM;
    const int bcol = blockIdx.x * BN;
    const int wm = (warp >> 1) * 32;
    const int wn = (warp & 1) * 64;

    const int lr = t >> 2;
    const int lc = (t & 3) * 8;
    const __half* Ag = A + (size_t)(brow + lr) * K + lc;
    const __half* Wg = W + (size_t)(bcol + lr) * K + lc;

    const int arow = lane & 15;
    const int acol = (lane & 16) >> 1;
    const int browl = (lane & 7) + ((lane & 16) >> 1);
    const int bcoll = lane & 8;

    float acc[2][8][4];
#pragma unroll
    for (int a = 0; a < 2; a++)
#pragma unroll
        for (int b = 0; b < 8; b++)
#pragma unroll
            for (int c = 0; c < 4; c++) acc[a][b][c] = 0.f;

    auto load_stage = [&](int i, int slot) {
        const int ko = i * BK;
        const uint32_t as = as_u + slot * ASTG * 2;
        const uint32_t ws = ws_u + slot * WSTG * 2;
        cp_async16(as + (lr * LDS + lc) * 2,        Ag + ko);
        cp_async16(as + ((lr + 64) * LDS + lc) * 2, Ag + ko + (size_t)64 * K);
        cp_async16(ws + (lr * LDS + lc) * 2,        Wg + ko);
        cp_async16(ws + ((lr + 64) * LDS + lc) * 2, Wg + ko + (size_t)64 * K);
        asm volatile("cp.async.commit_group;\n");
    };

    load_stage(0, 0);
    load_stage(1, 1);

    for (int i = 0; i < NT; i++) {
        if (i + 1 < NT) asm volatile("cp.async.wait_group 1;\n");
        else            asm volatile("cp.async.wait_group 0;\n");
        __syncthreads();   // single barrier per K-iter

        if (i + 2 < NT) load_stage(i + 2, (i + 2) % NSTAGE);

        const int s = i % NSTAGE;
        const uint32_t as = as_u + s * ASTG * 2;
        const uint32_t ws = ws_u + s * WSTG * 2;

#pragma unroll
        for (int kk = 0; kk < BK; kk += 16) {
            uint32_t ra[2][4], rb[8][2];
#pragma unroll
            for (int mi = 0; mi < 2; mi++)
                ldsm_x4(ra[mi][0], ra[mi][1], ra[mi][2], ra[mi][3],
                        as + ((wm + mi * 16 + arow) * LDS + kk + acol) * 2);
#pragma unroll
            for (int np = 0; np < 4; np++)
                ldsm_x4(rb[2 * np][0], rb[2 * np][1], rb[2 * np + 1][0], rb[2 * np + 1][1],
                        ws + ((wn + np * 16 + browl) * LDS + kk + bcoll) * 2);
#pragma unroll
            for (int mi = 0; mi < 2; mi++)
#pragma unroll
                for (int ni = 0; ni < 8; ni++)
                    asm volatile(
                        "mma.sync.aligned.m16n8k16.row.col.f32.f16.f16.f32 "
                        "{%0,%1,%2,%3}, {%4,%5,%6,%7}, {%8,%9}, {%0,%1,%2,%3};"
                        : "+f"(acc[mi][ni][0]), "+f"(acc[mi][ni][1]),
                          "+f"(acc[mi][ni][2]), "+f"(acc[mi][ni][3])
                        : "r"(ra[mi][0]), "r"(ra[mi][1]), "r"(ra[mi][2]), "r"(ra[mi][3]),
                          "r"(rb[ni][0]), "r"(rb[ni][1]));
        }
    }

#pragma unroll
    for (int mi = 0; mi < 2; mi++) {
#pragma unroll
        for (int ni = 0; ni < 8; ni++) {
            int r0 = brow + wm + mi * 16 + g;
            int r1 = r0 + 8;
            int c0 = bcol + wn + ni * 8 + tg * 2;
            float v0 = acc[mi][ni][0], v1 = acc[mi][ni][1];
            float v2 = acc[mi][ni][2], v3 = acc[mi][ni][3];
            float b0 = bias[c0], b1 = bias[c0 + 1];
            v0 += b0; v1 += b1; v2 += b0; v3 += b1;
            if (relu) {
                v0 = fmaxf(v0, 0.f); v1 = fmaxf(v1, 0.f);
                v2 = fmaxf(v2, 0.f); v3 = fmaxf(v3, 0.f);
            }
            if (resh) {
                float2 f0 = __half22float2(*(const __half2*)&resh[(size_t)r0 * EDIM + c0]);
                float2 f1 = __half22float2(*(const __half2*)&resh[(size_t)r1 * EDIM + c0]);
                v0 += f0.x; v1 += f0.y; v2 += f1.x; v3 += f1.y;
            }
            *(__half2*)&outh[(size_t)r0 * N + c0] = __floats2half2_rn(v0, v1);
            *(__half2*)&outh[(size_t)r1 * N + c0] = __floats2half2_rn(v2, v3);
        }
    }
}

// ------------------------- row LayerNorm (E=512, fp16 in) ---------------------
__global__ void k_ln(const __half* __restrict__ x,
                     const float* __restrict__ gam, const float* __restrict__ bet,
                     __half* __restrict__ outh, float* __restrict__ outf,
                     int ld_out, int coloff)
{
    int row = blockIdx.x;
    int t = threadIdx.x;  // 128 threads
    const __half2* xr = (const __half2*)(x + (size_t)row * EDIM);
    float2 v[2];
    float s = 0.f, sq = 0.f;
#pragma unroll
    for (int i = 0; i < 2; i++) {
        v[i] = __half22float2(xr[t + i * 128]);
        s  += v[i].x + v[i].y;
        sq += v[i].x * v[i].x + v[i].y * v[i].y;
    }
#pragma unroll
    for (int o = 16; o > 0; o >>= 1) {
        s  += __shfl_xor_sync(0xFFFFFFFFu, s, o);
        sq += __shfl_xor_sync(0xFFFFFFFFu, sq, o);
    }
    __shared__ float ss[4], ssq[4];
    int w = t >> 5, l = t & 31;
    if (l == 0) { ss[w] = s; ssq[w] = sq; }
    __syncthreads();
    s  = ss[0] + ss[1] + ss[2] + ss[3];
    sq = ssq[0] + ssq[1] + ssq[2] + ssq[3];
    float mean = s * (1.f / EDIM);
    float var  = sq * (1.f / EDIM) - mean * mean;
    float rstd = rsqrtf(var + 1e-5f);
#pragma unroll
    for (int i = 0; i < 2; i++) {
        int c = 2 * (t + i * 128);
        float y0 = (v[i].x - mean) * rstd * gam[c]     + bet[c];
        float y1 = (v[i].y - mean) * rstd * gam[c + 1] + bet[c + 1];
        if (outh) *(__half2*)&outh[(size_t)row * EDIM + c] = __floats2half2_rn(y0, y1);
        if (outf) {
            outf[(size_t)row * ld_out + coloff + c]     = y0;
            outf[(size_t)row * ld_out + coloff + c + 1] = y1;
        }
    }
}

// ------------------------------- launch ---------------------------------------
extern "C" void kernel_launch(void* const* d_in, const int* in_sizes, int n_in,
                              void* d_out, int out_size) {
    const float* a_in_w[2]  = { (const float*)d_in[2], (const float*)d_in[6] };
    const float* a_in_b[2]  = { (const float*)d_in[3], (const float*)d_in[7] };
    const float* a_out_w[2] = { (const float*)d_in[4], (const float*)d_in[8] };
    const float* a_out_b[2] = { (const float*)d_in[5], (const float*)d_in[9] };
    const float* lnA_g[2] = { (const float*)d_in[10], (const float*)d_in[12] };
    const float* lnA_b[2] = { (const float*)d_in[11], (const float*)d_in[13] };
    const float* lnB_g[2] = { (const float*)d_in[14], (const float*)d_in[16] };
    const float* lnB_b[2] = { (const float*)d_in[15], (const float*)d_in[17] };
    const float* f_w1[2] = { (const float*)d_in[18], (const float*)d_in[22] };
    const float* f_b1[2] = { (const float*)d_in[19], (const float*)d_in[23] };
    const float* f_w2[2] = { (const float*)d_in[20], (const float*)d_in[24] };
    const float* f_b2[2] = { (const float*)d_in[21], (const float*)d_in[25] };
    float* out = (float*)d_out;

    __half *xh[2], *hb, *ub, *tb, *wc, *w1h, *w2h;
    float *cbuf;
    cudaGetSymbolAddress((void**)&xh[0], g_xh0);
    cudaGetSymbolAddress((void**)&xh[1], g_xh1);
    cudaGetSymbolAddress((void**)&hb,   g_h);
    cudaGetSymbolAddress((void**)&ub,   g_u);
    cudaGetSymbolAddress((void**)&tb,   g_t16);
    cudaGetSymbolAddress((void**)&wc,   g_wc);
    cudaGetSymbolAddress((void**)&cbuf, g_c);
    cudaGetSymbolAddress((void**)&w1h,  g_w1h);
    cudaGetSymbolAddress((void**)&w2h,  g_w2h);

    __half* h [2] = { hb, hb + (size_t)MROWS * EDIM };
    __half* u [2] = { ub, ub + (size_t)MROWS * FFDIM };
    __half* tt[2] = { tb, tb + (size_t)MROWS * EDIM };

    cudaFuncSetAttribute(k_gemm<EDIM>,
                         cudaFuncAttributeMaxDynamicSharedMemorySize, GEMM_SMEM);
    cudaFuncSetAttribute(k_gemm<FFDIM>,
                         cudaFuncAttributeMaxDynamicSharedMemorySize, GEMM_SMEM);

    // one-time stream/event setup (resources only; captured WORK is identical
    // on every call)
    static cudaStream_t br[2] = {nullptr, nullptr};
    static cudaEvent_t evRoot = nullptr, evAct = nullptr, evD[2] = {nullptr, nullptr};
    if (!br[0]) {
        cudaStreamCreateWithFlags(&br[0], cudaStreamNonBlocking);
        cudaStreamCreateWithFlags(&br[1], cudaStreamNonBlocking);
        cudaEventCreateWithFlags(&evRoot, cudaEventDisableTiming);
        cudaEventCreateWithFlags(&evAct,  cudaEventDisableTiming);
        cudaEventCreateWithFlags(&evD[0], cudaEventDisableTiming);
        cudaEventCreateWithFlags(&evD[1], cudaEventDisableTiming);
    }

    const int NXE = MROWS * EDIM;

    // fork point (before any work): branches start with weight prep
    cudaEventRecord(evRoot, 0);
    cudaStreamWaitEvent(br[0], evRoot, 0);
    cudaStreamWaitEvent(br[1], evRoot, 0);

    // main stream: activation converts
    k_f2h<<<NXE / 1024, 256>>>((const float*)d_in[0], xh[0], NXE);
    k_f2h<<<NXE / 1024, 256>>>((const float*)d_in[1], xh[1], NXE);
    cudaEventRecord(evAct, 0);

    dim3 gE(EDIM / BN, MROWS / BM);    // (4, 256)
    dim3 gF(FFDIM / BN, MROWS / BM);   // (8, 256)

    for (int s = 0; s < 2; s++) {
        cudaStream_t st = br[s];
        __half* w1s = w1h + (size_t)s * FFDIM * EDIM;
        __half* w2s = w2h + (size_t)s * EDIM * FFDIM;
        __half* wcs = wc  + (size_t)s * EDIM * EDIM;
        float*  ccs = cbuf + s * EDIM;

        // weight prep (independent of activations)
        k_f2h<<<(FFDIM * EDIM) / 1024, 256, 0, st>>>(f_w1[s], w1s, FFDIM * EDIM);
        k_f2h<<<(EDIM * FFDIM) / 1024, 256, 0, st>>>(f_w2[s], w2s, EDIM * FFDIM);
        k_fold<<<EDIM, EDIM, 0, st>>>(a_out_w[s], a_in_w[s] + 2 * EDIM * EDIM, wcs);
        k_foldc<<<2, 256, 0, st>>>(a_out_w[s], a_out_b[s], a_in_b[s] + 2 * EDIM, ccs);

        // activations ready?
        cudaStreamWaitEvent(st, evAct, 0);

        const __half* kv = xh[1 - s];
        // t = x_s + kv @ Wc^T + c
        k_gemm<EDIM><<<gE, 256, GEMM_SMEM, st>>>(kv, wcs, ccs, xh[s], tt[s], EDIM, 0);
        // h = LN(t)
        k_ln<<<MROWS, 128, 0, st>>>(tt[s], lnA_g[s], lnA_b[s], h[s], nullptr, 0, 0);
        // u = relu(h @ w1^T + b1)
        k_gemm<EDIM><<<gF, 256, GEMM_SMEM, st>>>(h[s], w1s, f_b1[s], nullptr, u[s], FFDIM, 1);
        // t = h + u @ w2^T + b2
        k_gemm<FFDIM><<<gE, 256, GEMM_SMEM, st>>>(u[s], w2s, f_b2[s], h[s], tt[s], EDIM, 0);
        // out[:, s*512:(s+1)*512] = LN(t)
        k_ln<<<MROWS, 128, 0, st>>>(tt[s], lnB_g[s], lnB_b[s], nullptr, out, 2 * EDIM, s * EDIM);

        cudaEventRecord(evD[s], st);
    }

    // join
    cudaStreamWaitEvent(0, evD[0], 0);
    cudaStreamWaitEvent(0, evD[1], 0);
}